// round 16
// baseline (speedup 1.0000x reference)
#include <cuda_runtime.h>
#include <cuda_fp16.h>
#include <cstdint>

#define NIT 64                     // K=4096 in 64-wide slabs
#define A_BYTES 16384              // 128 rows x 128B
#define B_BYTES 16384              // 128 rows x 128B
#define STAGE_BYTES (A_BYTES + B_BYTES)
#define SMEM_TOTAL (3*STAGE_BYTES + 256)   // 2 CTAs/SM
#define SG_STRIDE 130              // epilogue smem row stride (floats)

// g_Ah rows INTERLEAVED: row' = m*4 + gate  (CTA A-tile = contiguous 128 rows)
__device__ __half g_Ah[(size_t)8192 * 4096];
__device__ __half g_Bh[(size_t)4096 * 4096];  // [batch][k] = x^T || h, fp16
__device__ float  g_S[4096];                  // per-batch operand sums (fp32)

__device__ __forceinline__ uint32_t smem_u32(const void* p) {
    uint32_t a;
    asm("{ .reg .u64 t; cvta.to.shared.u64 t, %1; cvt.u32.u64 %0, t; }" : "=r"(a) : "l"(p));
    return a;
}
__device__ __forceinline__ float sigmf(float z) { return 1.0f / (1.0f + __expf(-z)); }

// ---------------- pre-pass ----------------
__global__ void convA(const float* __restrict__ a0, const float* __restrict__ a1,
                      const float* __restrict__ a2, const float* __restrict__ a3,
                      const float* __restrict__ h0, const float* __restrict__ h1,
                      const float* __restrict__ h2, const float* __restrict__ h3) {
    size_t i8 = (size_t)blockIdx.x * 256 + threadIdx.x;
    size_t flat = i8 << 3;
    int rp = (int)(flat >> 12);          // interleaved row = m*4+g
    int k  = (int)(flat & 4095);
    int m = rp >> 2, g = rp & 3;
    const float* w = (k < 2048)
        ? ((g == 0) ? a0 : (g == 1) ? a1 : (g == 2) ? a2 : a3)
        : ((g == 0) ? h0 : (g == 1) ? h1 : (g == 2) ? h2 : h3);
    const float* src = w + (size_t)m * 2048 + (k & 2047);
    float4 v0 = *(const float4*)src;
    float4 v1 = *(const float4*)(src + 4);
    __half h8[8];
    h8[0] = __float2half_rn(v0.x - 0.2f); h8[1] = __float2half_rn(v0.y - 0.2f);
    h8[2] = __float2half_rn(v0.z - 0.2f); h8[3] = __float2half_rn(v0.w - 0.2f);
    h8[4] = __float2half_rn(v1.x - 0.2f); h8[5] = __float2half_rn(v1.y - 0.2f);
    h8[6] = __float2half_rn(v1.z - 0.2f); h8[7] = __float2half_rn(v1.w - 0.2f);
    *(uint4*)(g_Ah + flat) = *(uint4*)h8;
}

__global__ void convBh(const float* __restrict__ h) {
    __shared__ float red[256];
    const int n = blockIdx.x, t = threadIdx.x;
    const float* src = h + (size_t)n * 2048 + t * 8;
    float4 v0 = *(const float4*)src;
    float4 v1 = *(const float4*)(src + 4);
    __half h8[8];
    h8[0] = __float2half_rn(v0.x); h8[1] = __float2half_rn(v0.y);
    h8[2] = __float2half_rn(v0.z); h8[3] = __float2half_rn(v0.w);
    h8[4] = __float2half_rn(v1.x); h8[5] = __float2half_rn(v1.y);
    h8[6] = __float2half_rn(v1.z); h8[7] = __float2half_rn(v1.w);
    *(uint4*)(g_Bh + (size_t)n * 4096 + 2048 + t * 8) = *(uint4*)h8;
    red[t] = ((v0.x + v0.y) + (v0.z + v0.w)) + ((v1.x + v1.y) + (v1.z + v1.w));
    __syncthreads();
    for (int st = 128; st > 0; st >>= 1) {
        if (t < st) red[t] += red[t + st];
        __syncthreads();
    }
    if (t == 0) g_S[n] = red[0];
}

__global__ void convBx(const float* __restrict__ x) {
    __shared__ float t[32][33];
    const int n0 = blockIdx.x << 5, k0 = blockIdx.y << 5;
    const int tx = threadIdx.x, ty = threadIdx.y;
#pragma unroll
    for (int i = 0; i < 4; ++i)
        t[ty + i * 8][tx] = x[(size_t)(k0 + ty + i * 8) * 4096 + n0 + tx];
    __syncthreads();
#pragma unroll
    for (int i = 0; i < 4; ++i) {
        int n = ty + i * 8;
        g_Bh[(size_t)(n0 + n) * 4096 + k0 + tx] = __float2half_rn(t[tx][n]);
    }
    if (ty == 0) {
        float s = 0.0f;
#pragma unroll
        for (int ky = 0; ky < 32; ++ky) s += t[ky][tx];
        atomicAdd(g_S + n0 + tx, s);
    }
}

// ---------------- fused fp16 GEMM + LSTM epilogue ----------------
// CTA: 256 threads (8 warps), tile 128 A-rows x 128 n. Warp tile 64x32.
#define LOAD_STAGE(stg) do { \
    uint32_t da_ = sbase + (uint32_t)(stg) * STAGE_BYTES + dst0; \
    const __half* pa_ = srcA; \
    _Pragma("unroll") \
    for (int q_ = 0; q_ < 4; ++q_) { \
        asm volatile("cp.async.cg.shared.global [%0], [%1], 16;" :: "r"(da_), "l"(pa_)); \
        da_ += 4096; pa_ += (size_t)32 * 4096; \
    } \
    uint32_t db_ = sbase + (uint32_t)(stg) * STAGE_BYTES + A_BYTES + dst0; \
    const __half* pb_ = srcB; \
    _Pragma("unroll") \
    for (int q_ = 0; q_ < 4; ++q_) { \
        asm volatile("cp.async.cg.shared.global [%0], [%1], 16;" :: "r"(db_), "l"(pb_)); \
        db_ += 4096; pb_ += (size_t)32 * 4096; \
    } \
    asm volatile("cp.async.commit_group;"); \
    srcA += 64; srcB += 64; \
} while (0)

// One A ldmatrix.x4 for row-block i, swizzle folded into a single XOR.
#define LDA1(i_, xv_) do { \
    uint32_t t_ = (sAa ^ (uint32_t)(xv_)) + (i_) * 2048; \
    asm volatile("ldmatrix.sync.aligned.m8n8.x4.shared.b16 {%0,%1,%2,%3}, [%4];" \
        : "=r"(av[i_][0]), "=r"(av[i_][1]), "=r"(av[i_][2]), "=r"(av[i_][3]) \
        : "r"(t_)); \
} while (0)

// Both B ldmatrix.x4 for one k-step into buffer buf_.
#define LDB2(buf_, xv_) do { \
    uint32_t t_ = sBb ^ (uint32_t)(xv_); \
    asm volatile("ldmatrix.sync.aligned.m8n8.x4.shared.b16 {%0,%1,%2,%3}, [%4];" \
        : "=r"(bv[buf_][0][0]), "=r"(bv[buf_][0][1]), \
          "=r"(bv[buf_][0][2]), "=r"(bv[buf_][0][3]) : "r"(t_)); \
    asm volatile("ldmatrix.sync.aligned.m8n8.x4.shared.b16 {%0,%1,%2,%3}, [%4];" \
        : "=r"(bv[buf_][1][0]), "=r"(bv[buf_][1][1]), \
          "=r"(bv[buf_][1][2]), "=r"(bv[buf_][1][3]) : "r"(t_ + 2048)); \
} while (0)

// 4 MMAs of m-group i_ against B buffer buf_.
#define MMAG(i_, buf_) do { \
    _Pragma("unroll") \
    for (int j_ = 0; j_ < 4; ++j_) \
        asm volatile( \
            "mma.sync.aligned.m16n8k16.row.col.f32.f16.f16.f32 " \
            "{%0,%1,%2,%3}, {%4,%5,%6,%7}, {%8,%9}, {%0,%1,%2,%3};" \
            : "+f"(acc[i_][j_][0]), "+f"(acc[i_][j_][1]), \
              "+f"(acc[i_][j_][2]), "+f"(acc[i_][j_][3]) \
            : "r"(av[i_][0]), "r"(av[i_][1]), "r"(av[i_][2]), "r"(av[i_][3]), \
              "r"(bv[buf_][j_ >> 1][(j_ & 1) * 2]), \
              "r"(bv[buf_][j_ >> 1][(j_ & 1) * 2 + 1])); \
} while (0)

__global__ void __launch_bounds__(256, 2) gemm_fused(
    const float* __restrict__ c_in,
    const float* __restrict__ b_ii, const float* __restrict__ b_hi,
    const float* __restrict__ b_if, const float* __restrict__ b_hf,
    const float* __restrict__ b_ig, const float* __restrict__ b_hg,
    const float* __restrict__ b_io, const float* __restrict__ b_ho,
    float* __restrict__ out)
{
    extern __shared__ char smem[];
    const uint32_t sbase = (smem_u32(smem) + 127u) & ~127u;
    const int tid = threadIdx.x;
    const int bm = blockIdx.x >> 5, bn = blockIdx.x & 31;   // 64 x 32 tiles

    // cp.async bases: 32 rows per pass, 4 passes per operand
    const int r0 = tid >> 3, c0 = tid & 7;
    const uint32_t dst0 = (uint32_t)(r0 * 128 + ((c0 ^ (r0 & 7)) << 4));
    const __half* srcA = g_Ah + (size_t)(bm * 128 + r0) * 4096 + c0 * 8;
    const __half* srcB = g_Bh + (size_t)(bn * 128 + r0) * 4096 + c0 * 8;

    const int lane = tid & 31, wid = tid >> 5;
    const int wm = wid & 1, wn = wid >> 1;            // warp tile 64m x 32n
    const int arow_l = wm * 64 + ((lane >> 3) & 1) * 8 + (lane & 7);
    const int brow_l = wn * 32 + ((lane >> 4) & 1) * 8 + (lane & 7);
    // swizzle-folded bases: addr = (sAa ^ ((ks*2+kch)<<4)) + i*2048
    const uint32_t aoff0 = (uint32_t)(arow_l * 128 + ((arow_l & 7) << 4));
    const uint32_t boff0 = (uint32_t)(brow_l * 128 + ((brow_l & 7) << 4));
    const uint32_t axor = (uint32_t)((lane >> 4) << 4);        // akch_l<<4
    const uint32_t bxor = (uint32_t)(((lane >> 3) & 1) << 4);  // bkch_l<<4

    float acc[4][4][4];
#pragma unroll
    for (int i = 0; i < 4; ++i)
#pragma unroll
        for (int j = 0; j < 4; ++j)
#pragma unroll
            for (int r = 0; r < 4; ++r) acc[i][j][r] = 0.0f;

    uint32_t av[4][4], bv[2][2][4];

    LOAD_STAGE(0);
    LOAD_STAGE(1);

    for (int it = 0; it < NIT; ++it) {
        if (it + 1 < NIT) asm volatile("cp.async.wait_group 1;");
        else              asm volatile("cp.async.wait_group 0;");
        __syncthreads();

        const uint32_t sA = sbase + (uint32_t)(it % 3) * STAGE_BYTES;
        const uint32_t sAa = sA + aoff0;
        const uint32_t sBb = sA + A_BYTES + boff0;

        // k-step 0 operands
        LDA1(0, axor); LDA1(1, axor); LDA1(2, axor); LDA1(3, axor);
        LDB2(0, bxor);
        if (it + 2 < NIT) LOAD_STAGE((it + 2) % 3);

        // ks=0 : prefetch B(1), interleave A(1) after each m-group
        LDB2(1, 32 | bxor);
        MMAG(0, 0); LDA1(0, 32 | axor);
        MMAG(1, 0); LDA1(1, 32 | axor);
        MMAG(2, 0); LDA1(2, 32 | axor);
        MMAG(3, 0); LDA1(3, 32 | axor);
        // ks=1 : prefetch B(2), A(2)
        LDB2(0, 64 | bxor);
        MMAG(0, 1); LDA1(0, 64 | axor);
        MMAG(1, 1); LDA1(1, 64 | axor);
        MMAG(2, 1); LDA1(2, 64 | axor);
        MMAG(3, 1); LDA1(3, 64 | axor);
        // ks=2 : prefetch B(3), A(3)
        LDB2(1, 96 | bxor);
        MMAG(0, 0); LDA1(0, 96 | axor);
        MMAG(1, 0); LDA1(1, 96 | axor);
        MMAG(2, 0); LDA1(2, 96 | axor);
        MMAG(3, 0); LDA1(3, 96 | axor);
        // ks=3
        MMAG(0, 1); MMAG(1, 1); MMAG(2, 1); MMAG(3, 1);
    }
    __syncthreads();

    // ---- stage gates: local A-row = m*4+gate -> sG[gate][32 m][128 n] ----
    float* sG = (float*)smem;
    {
        const int rbase = lane >> 2;
        const int col = wn * 32 + (lane & 3) * 2;
#pragma unroll
        for (int i = 0; i < 4; ++i)
#pragma unroll
            for (int rr = 0; rr < 2; ++rr) {
                int row = wm * 64 + i * 16 + rbase + rr * 8;
                float* p = sG + (size_t)(row & 3) * 32 * SG_STRIDE
                              + (row >> 2) * SG_STRIDE + col;
#pragma unroll
                for (int j = 0; j < 4; ++j)
                    *(float2*)(p + j * 8) =
                        make_float2(acc[i][j][rr * 2], acc[i][j][rr * 2 + 1]);
            }
    }
    __syncthreads();

    // ---- LSTM epilogue, coalesced along m (warp = 32 consecutive m) ----
    const int m_l = tid & 31, nq = tid >> 5;
    const int m_g = bm * 32 + m_l;
    const float bsi = b_ii[m_g] + b_hi[m_g];
    const float bsf = b_if[m_g] + b_hf[m_g];
    const float bsg = b_ig[m_g] + b_hg[m_g];
    const float bso = b_io[m_g] + b_ho[m_g];
    float* out_c = out + (size_t)4096 * 2048;
    const float* row0 = sG + m_l * SG_STRIDE;
#pragma unroll 4
    for (int loop = 0; loop < 16; ++loop) {
        const int n_l = loop * 8 + nq;
        const int n_g = bn * 128 + n_l;
        const float s2 = 0.2f * g_S[n_g];
        float iv = sigmf(row0[0 * 32 * SG_STRIDE + n_l] + s2 + bsi);
        float fv = sigmf(row0[1 * 32 * SG_STRIDE + n_l] + s2 + bsf);
        float gv = tanhf(row0[2 * 32 * SG_STRIDE + n_l] + s2 + bsg);
        float ov = sigmf(row0[3 * 32 * SG_STRIDE + n_l] + s2 + bso);
        float cv = c_in[(size_t)n_g * 2048 + m_g];
        float cn = fv * cv + iv * gv;
        out_c[(size_t)n_g * 2048 + m_g] = cn;
        out[(size_t)n_g * 2048 + m_g]   = ov * tanhf(cn);
    }
}

// ---------------- launcher ----------------
extern "C" void kernel_launch(void* const* d_in, const int* in_sizes, int n_in,
                              void* d_out, int out_size)
{
    (void)in_sizes; (void)n_in; (void)out_size;
    const float* x = (const float*)d_in[0];
    const float* h = (const float*)d_in[1];
    const float* c = (const float*)d_in[2];

    cudaFuncSetAttribute(gemm_fused, cudaFuncAttributeMaxDynamicSharedMemorySize, SMEM_TOTAL);

    convA<<<16384, 256>>>((const float*)d_in[3], (const float*)d_in[4],
                          (const float*)d_in[5], (const float*)d_in[6],
                          (const float*)d_in[7], (const float*)d_in[8],
                          (const float*)d_in[9], (const float*)d_in[10]);
    convBh<<<4096, 256>>>(h);
    convBx<<<dim3(128, 64), dim3(32, 8)>>>(x);

    gemm_fused<<<2048, 256, SMEM_TOTAL>>>(
        c,
        (const float*)d_in[11], (const float*)d_in[12],
        (const float*)d_in[13], (const float*)d_in[14],
        (const float*)d_in[15], (const float*)d_in[16],
        (const float*)d_in[17], (const float*)d_in[18],
        (float*)d_out);
}

// round 17
// speedup vs baseline: 1.0083x; 1.0083x over previous
#include <cuda_runtime.h>
#include <cuda_fp16.h>
#include <cstdint>

#define NIT 64                     // K=4096 in 64-wide slabs
#define A_BYTES 16384              // 128 rows x 128B
#define B_BYTES 16384              // 128 rows x 128B
#define STAGE_BYTES (A_BYTES + B_BYTES)
#define SMEM_TOTAL (3*STAGE_BYTES + 256)   // 2 CTAs/SM
#define SG_STRIDE 130              // epilogue smem row stride (floats)

// g_Ah rows INTERLEAVED: row' = m*4 + gate  (CTA A-tile = contiguous 128 rows)
__device__ __half g_Ah[(size_t)8192 * 4096];
__device__ __half g_Bh[(size_t)4096 * 4096];  // [batch][k] = x^T || h, fp16
__device__ float  g_S[4096];                  // per-batch operand sums (fp32)

__device__ __forceinline__ uint32_t smem_u32(const void* p) {
    uint32_t a;
    asm("{ .reg .u64 t; cvta.to.shared.u64 t, %1; cvt.u32.u64 %0, t; }" : "=r"(a) : "l"(p));
    return a;
}
__device__ __forceinline__ float sigmf(float z) { return 1.0f / (1.0f + __expf(-z)); }

// ---------------- pre-pass ----------------
__global__ void convA(const float* __restrict__ a0, const float* __restrict__ a1,
                      const float* __restrict__ a2, const float* __restrict__ a3,
                      const float* __restrict__ h0, const float* __restrict__ h1,
                      const float* __restrict__ h2, const float* __restrict__ h3) {
    size_t i8 = (size_t)blockIdx.x * 256 + threadIdx.x;
    size_t flat = i8 << 3;
    int rp = (int)(flat >> 12);          // interleaved row = m*4+g
    int k  = (int)(flat & 4095);
    int m = rp >> 2, g = rp & 3;
    const float* w = (k < 2048)
        ? ((g == 0) ? a0 : (g == 1) ? a1 : (g == 2) ? a2 : a3)
        : ((g == 0) ? h0 : (g == 1) ? h1 : (g == 2) ? h2 : h3);
    const float* src = w + (size_t)m * 2048 + (k & 2047);
    float4 v0 = *(const float4*)src;
    float4 v1 = *(const float4*)(src + 4);
    __half h8[8];
    h8[0] = __float2half_rn(v0.x - 0.2f); h8[1] = __float2half_rn(v0.y - 0.2f);
    h8[2] = __float2half_rn(v0.z - 0.2f); h8[3] = __float2half_rn(v0.w - 0.2f);
    h8[4] = __float2half_rn(v1.x - 0.2f); h8[5] = __float2half_rn(v1.y - 0.2f);
    h8[6] = __float2half_rn(v1.z - 0.2f); h8[7] = __float2half_rn(v1.w - 0.2f);
    *(uint4*)(g_Ah + flat) = *(uint4*)h8;
}

__global__ void convBh(const float* __restrict__ h) {
    __shared__ float red[256];
    const int n = blockIdx.x, t = threadIdx.x;
    const float* src = h + (size_t)n * 2048 + t * 8;
    float4 v0 = *(const float4*)src;
    float4 v1 = *(const float4*)(src + 4);
    __half h8[8];
    h8[0] = __float2half_rn(v0.x); h8[1] = __float2half_rn(v0.y);
    h8[2] = __float2half_rn(v0.z); h8[3] = __float2half_rn(v0.w);
    h8[4] = __float2half_rn(v1.x); h8[5] = __float2half_rn(v1.y);
    h8[6] = __float2half_rn(v1.z); h8[7] = __float2half_rn(v1.w);
    *(uint4*)(g_Bh + (size_t)n * 4096 + 2048 + t * 8) = *(uint4*)h8;
    red[t] = ((v0.x + v0.y) + (v0.z + v0.w)) + ((v1.x + v1.y) + (v1.z + v1.w));
    __syncthreads();
    for (int st = 128; st > 0; st >>= 1) {
        if (t < st) red[t] += red[t + st];
        __syncthreads();
    }
    if (t == 0) g_S[n] = red[0];
}

__global__ void convBx(const float* __restrict__ x) {
    __shared__ float t[32][33];
    const int n0 = blockIdx.x << 5, k0 = blockIdx.y << 5;
    const int tx = threadIdx.x, ty = threadIdx.y;
#pragma unroll
    for (int i = 0; i < 4; ++i)
        t[ty + i * 8][tx] = x[(size_t)(k0 + ty + i * 8) * 4096 + n0 + tx];
    __syncthreads();
#pragma unroll
    for (int i = 0; i < 4; ++i) {
        int n = ty + i * 8;
        g_Bh[(size_t)(n0 + n) * 4096 + k0 + tx] = __float2half_rn(t[tx][n]);
    }
    if (ty == 0) {
        float s = 0.0f;
#pragma unroll
        for (int ky = 0; ky < 32; ++ky) s += t[ky][tx];
        atomicAdd(g_S + n0 + tx, s);
    }
}

// ---------------- fused fp16 GEMM + LSTM epilogue ----------------
// CTA: 256 threads (8 warps), tile 128 A-rows x 128 n. Warp tile 64x32.
#define LOAD_STAGE(stg) do { \
    uint32_t da_ = sbase + (uint32_t)(stg) * STAGE_BYTES + dst0; \
    const __half* pa_ = srcA; \
    _Pragma("unroll") \
    for (int q_ = 0; q_ < 4; ++q_) { \
        asm volatile("cp.async.cg.shared.global [%0], [%1], 16;" :: "r"(da_), "l"(pa_)); \
        da_ += 4096; pa_ += (size_t)32 * 4096; \
    } \
    uint32_t db_ = sbase + (uint32_t)(stg) * STAGE_BYTES + A_BYTES + dst0; \
    const __half* pb_ = srcB; \
    _Pragma("unroll") \
    for (int q_ = 0; q_ < 4; ++q_) { \
        asm volatile("cp.async.cg.shared.global [%0], [%1], 16;" :: "r"(db_), "l"(pb_)); \
        db_ += 4096; pb_ += (size_t)32 * 4096; \
    } \
    asm volatile("cp.async.commit_group;"); \
    srcA += 64; srcB += 64; \
} while (0)

#define LDFRAG(ks) do { \
    const int chA_ = (ks) * 2 + akch_l; \
    _Pragma("unroll") \
    for (int i_ = 0; i_ < 4; ++i_) { \
        int row_ = i_ * 16 + arow_l; \
        uint32_t ad_ = sA + (uint32_t)(row_ * 128 + ((chA_ ^ (row_ & 7)) << 4)); \
        asm volatile("ldmatrix.sync.aligned.m8n8.x4.shared.b16 {%0,%1,%2,%3}, [%4];" \
            : "=r"(av[i_][0]), "=r"(av[i_][1]), \
              "=r"(av[i_][2]), "=r"(av[i_][3]) : "r"(ad_)); \
    } \
    const int chB_ = (ks) * 2 + bkch_l; \
    _Pragma("unroll") \
    for (int j_ = 0; j_ < 2; ++j_) { \
        int row_ = brow_l + j_ * 16; \
        uint32_t bd_ = sB + (uint32_t)(row_ * 128 + ((chB_ ^ (row_ & 7)) << 4)); \
        asm volatile("ldmatrix.sync.aligned.m8n8.x4.shared.b16 {%0,%1,%2,%3}, [%4];" \
            : "=r"(bv[j_][0]), "=r"(bv[j_][1]), \
              "=r"(bv[j_][2]), "=r"(bv[j_][3]) : "r"(bd_)); \
    } \
} while (0)

#define DO_MMAS() do { \
    _Pragma("unroll") \
    for (int i_ = 0; i_ < 4; ++i_) \
    _Pragma("unroll") \
    for (int j_ = 0; j_ < 4; ++j_) \
        asm volatile( \
            "mma.sync.aligned.m16n8k16.row.col.f32.f16.f16.f32 " \
            "{%0,%1,%2,%3}, {%4,%5,%6,%7}, {%8,%9}, {%0,%1,%2,%3};" \
            : "+f"(acc[i_][j_][0]), "+f"(acc[i_][j_][1]), \
              "+f"(acc[i_][j_][2]), "+f"(acc[i_][j_][3]) \
            : "r"(av[i_][0]), "r"(av[i_][1]), \
              "r"(av[i_][2]), "r"(av[i_][3]), \
              "r"(bv[j_ >> 1][(j_ & 1) * 2]), \
              "r"(bv[j_ >> 1][(j_ & 1) * 2 + 1])); \
} while (0)

__global__ void __launch_bounds__(256, 2) gemm_fused(
    const float* __restrict__ c_in,
    const float* __restrict__ b_ii, const float* __restrict__ b_hi,
    const float* __restrict__ b_if, const float* __restrict__ b_hf,
    const float* __restrict__ b_ig, const float* __restrict__ b_hg,
    const float* __restrict__ b_io, const float* __restrict__ b_ho,
    float* __restrict__ out)
{
    extern __shared__ char smem[];
    const uint32_t sbase = (smem_u32(smem) + 127u) & ~127u;
    const int tid = threadIdx.x;
    const int bm = blockIdx.x >> 5, bn = blockIdx.x & 31;   // 64 x 32 tiles

    // cp.async bases: 32 rows per pass, 4 passes per operand
    const int r0 = tid >> 3, c0 = tid & 7;
    const uint32_t dst0 = (uint32_t)(r0 * 128 + ((c0 ^ (r0 & 7)) << 4));
    const __half* srcA = g_Ah + (size_t)(bm * 128 + r0) * 4096 + c0 * 8;
    const __half* srcB = g_Bh + (size_t)(bn * 128 + r0) * 4096 + c0 * 8;

    const int lane = tid & 31, wid = tid >> 5;
    const int wm = wid & 1, wn = wid >> 1;            // warp tile 64m x 32n
    const int arow_l = wm * 64 + ((lane >> 3) & 1) * 8 + (lane & 7);
    const int akch_l = lane >> 4;
    const int brow_l = wn * 32 + ((lane >> 4) & 1) * 8 + (lane & 7);
    const int bkch_l = (lane >> 3) & 1;

    float acc[4][4][4];
#pragma unroll
    for (int i = 0; i < 4; ++i)
#pragma unroll
        for (int j = 0; j < 4; ++j)
#pragma unroll
            for (int r = 0; r < 4; ++r) acc[i][j][r] = 0.0f;

    uint32_t av[4][4], bv[2][4];

    LOAD_STAGE(0);
    LOAD_STAGE(1);

    const bool oddw = (wid & 1) != 0;   // phase-rotated warps

    for (int it = 0; it < NIT; ++it) {
        if (it + 1 < NIT) asm volatile("cp.async.wait_group 1;");
        else              asm volatile("cp.async.wait_group 0;");
        __syncthreads();

        const uint32_t sA = sbase + (uint32_t)(it % 3) * STAGE_BYTES;
        const uint32_t sB = sA + A_BYTES;

        if (!oddw) {
            // even warps: k-steps 0,1,2,3
            LDFRAG(0);
            if (it + 2 < NIT) LOAD_STAGE((it + 2) % 3);
            DO_MMAS();
            LDFRAG(1); DO_MMAS();
            LDFRAG(2); DO_MMAS();
            LDFRAG(3); DO_MMAS();
        } else {
            // odd warps: k-steps 2,3,0,1 (same sum, staggered smem phases)
            LDFRAG(2);
            if (it + 2 < NIT) LOAD_STAGE((it + 2) % 3);
            DO_MMAS();
            LDFRAG(3); DO_MMAS();
            LDFRAG(0); DO_MMAS();
            LDFRAG(1); DO_MMAS();
        }
    }
    __syncthreads();

    // ---- stage gates: local A-row = m*4+gate -> sG[gate][32 m][128 n] ----
    float* sG = (float*)smem;
    {
        const int rbase = lane >> 2;
        const int col = wn * 32 + (lane & 3) * 2;
#pragma unroll
        for (int i = 0; i < 4; ++i)
#pragma unroll
            for (int rr = 0; rr < 2; ++rr) {
                int row = wm * 64 + i * 16 + rbase + rr * 8;
                float* p = sG + (size_t)(row & 3) * 32 * SG_STRIDE
                              + (row >> 2) * SG_STRIDE + col;
#pragma unroll
                for (int j = 0; j < 4; ++j)
                    *(float2*)(p + j * 8) =
                        make_float2(acc[i][j][rr * 2], acc[i][j][rr * 2 + 1]);
            }
    }
    __syncthreads();

    // ---- LSTM epilogue, coalesced along m (warp = 32 consecutive m) ----
    const int m_l = tid & 31, nq = tid >> 5;
    const int m_g = bm * 32 + m_l;
    const float bsi = b_ii[m_g] + b_hi[m_g];
    const float bsf = b_if[m_g] + b_hf[m_g];
    const float bsg = b_ig[m_g] + b_hg[m_g];
    const float bso = b_io[m_g] + b_ho[m_g];
    float* out_c = out + (size_t)4096 * 2048;
    const float* row0 = sG + m_l * SG_STRIDE;
#pragma unroll 4
    for (int loop = 0; loop < 16; ++loop) {
        const int n_l = loop * 8 + nq;
        const int n_g = bn * 128 + n_l;
        const float s2 = 0.2f * g_S[n_g];
        float iv = sigmf(row0[0 * 32 * SG_STRIDE + n_l] + s2 + bsi);
        float fv = sigmf(row0[1 * 32 * SG_STRIDE + n_l] + s2 + bsf);
        float gv = tanhf(row0[2 * 32 * SG_STRIDE + n_l] + s2 + bsg);
        float ov = sigmf(row0[3 * 32 * SG_STRIDE + n_l] + s2 + bso);
        float cv = c_in[(size_t)n_g * 2048 + m_g];
        float cn = fv * cv + iv * gv;
        out_c[(size_t)n_g * 2048 + m_g] = cn;
        out[(size_t)n_g * 2048 + m_g]   = ov * tanhf(cn);
    }
}

// ---------------- launcher ----------------
extern "C" void kernel_launch(void* const* d_in, const int* in_sizes, int n_in,
                              void* d_out, int out_size)
{
    (void)in_sizes; (void)n_in; (void)out_size;
    const float* x = (const float*)d_in[0];
    const float* h = (const float*)d_in[1];
    const float* c = (const float*)d_in[2];

    cudaFuncSetAttribute(gemm_fused, cudaFuncAttributeMaxDynamicSharedMemorySize, SMEM_TOTAL);

    convA<<<16384, 256>>>((const float*)d_in[3], (const float*)d_in[4],
                          (const float*)d_in[5], (const float*)d_in[6],
                          (const float*)d_in[7], (const float*)d_in[8],
                          (const float*)d_in[9], (const float*)d_in[10]);
    convBh<<<4096, 256>>>(h);
    convBx<<<dim3(128, 64), dim3(32, 8)>>>(x);

    gemm_fused<<<2048, 256, SMEM_TOTAL>>>(
        c,
        (const float*)d_in[11], (const float*)d_in[12],
        (const float*)d_in[13], (const float*)d_in[14],
        (const float*)d_in[15], (const float*)d_in[16],
        (const float*)d_in[17], (const float*)d_in[18],
        (float*)d_out);
}